// round 13
// baseline (speedup 1.0000x reference)
#include <cuda_runtime.h>
#include <math.h>
#include <stdint.h>

#define BB    4
#define SS    1024
#define HID_  768
#define HH    6
#define DD    64
#define AH_   384
#define KS_   9
#define PAD_  4

// ------------------------- scratch (static device mem) -------------------------
__device__ float g_mq [BB*SS*AH_];
__device__ float g_mk [BB*SS*AH_];
__device__ float g_mv [BB*SS*AH_];
__device__ float g_co [BB*SS*AH_];
__device__ float g_dw [BB*SS*HID_];
__device__ float g_mkc[BB*SS*AH_];
__device__ float g_cklg[BB*SS*64];     // ck logits, padded to 64 cols
__device__ float g_ckWp[AH_*64];       // ckW padded (384,54)->(384,64)
__device__ float g_ckbp[64];
__device__ float g_tdsm[BB*SS];
__device__ float g_scores[(size_t)BB*HH*SS*SS];   // 100 MB; scores then probs in-place

// ------------------------- fast math (FMA pipe, no MUFU) -------------------------
__device__ __forceinline__ float fexp(float x) {
    float t = x * 1.442695041f;
    t = fminf(fmaxf(t, -126.f), 126.f);
    float r  = t + 12582912.f;
    int   ei = __float_as_int(r) - 0x4B400000;
    float f  = t - (r - 12582912.f);
    float p = fmaf(f, 0.0013333558f, 0.0096181291f);
    p = fmaf(f, p, 0.0555041087f);
    p = fmaf(f, p, 0.2402265069f);
    p = fmaf(f, p, 0.6931471806f);
    p = fmaf(f, p, 1.0f);
    return p * __int_as_float((ei + 127) << 23);
}

__device__ __forceinline__ float fsqrt_(float x) {
    if (x <= 1.1754944e-38f) return 0.f;
    float y = __int_as_float(0x5f3759df - (__float_as_int(x) >> 1));
    y = y * fmaf(-0.5f * x * y, y, 1.5f);
    y = y * fmaf(-0.5f * x * y, y, 1.5f);
    return x * y;
}

// ------------------------- tf32 helpers -------------------------
__device__ __forceinline__ float tf32r(float x) {
    uint32_t r;
    asm("cvt.rna.tf32.f32 %0, %1;" : "=r"(r) : "f"(x));
    return __uint_as_float(r);
}

__device__ __forceinline__ void mma8(float* c, const uint32_t* a, uint32_t b0, uint32_t b1) {
    asm volatile("mma.sync.aligned.m16n8k8.row.col.f32.tf32.tf32.f32 "
        "{%0,%1,%2,%3}, {%4,%5,%6,%7}, {%8,%9}, {%0,%1,%2,%3};"
        : "+f"(c[0]), "+f"(c[1]), "+f"(c[2]), "+f"(c[3])
        : "r"(a[0]), "r"(a[1]), "r"(a[2]), "r"(a[3]), "r"(b0), "r"(b1));
}

// ------------------------- tf32 tensor-core GEMM core (128x64 tile) -------------------------
// 256 threads = 8 warps (4m x 2n), warp tile 32x32, k-step 16, reg-prefetch double buffer.
template<bool BNK, bool AMUL>
__device__ __forceinline__ void tgemm_core(
    const float* __restrict__ A, const float* __restrict__ A2,
    const float* __restrict__ B,
    const float* __restrict__ bias, float* __restrict__ C,
    int K, int lda, int ldb, int ldc, float scale, int m0, int n0)
{
    __shared__ float As[128][20];
    __shared__ float Bs[64][20];
    const int tid = threadIdx.x;
    const int warp = tid >> 5, lane = tid & 31;
    const int wm = (warp >> 1) * 32;
    const int wn = (warp & 1) * 32;
    const int grp = lane >> 2, qid = lane & 3;

    const int arow0 = (tid >> 2);
    const int akq   = (tid & 3) * 4;

    float c[2][4][4];
    #pragma unroll
    for (int mt = 0; mt < 2; mt++)
        #pragma unroll
        for (int nt = 0; nt < 4; nt++)
            #pragma unroll
            for (int r = 0; r < 4; r++) c[mt][nt][r] = 0.f;

    float4 pa[2], pb;

    auto loadg = [&](int k0) {
        #pragma unroll
        for (int it = 0; it < 2; it++) {
            int row = arow0 + it * 64;
            pa[it] = *(const float4*)&A[(size_t)(m0 + row) * lda + k0 + akq];
            if (AMUL) {
                float4 w = *(const float4*)&A2[(size_t)(m0 + row) * lda + k0 + akq];
                pa[it].x *= w.x; pa[it].y *= w.y; pa[it].z *= w.z; pa[it].w *= w.w;
            }
        }
        if (BNK) {
            int row = tid >> 2;
            pb = *(const float4*)&B[(size_t)(n0 + row) * ldb + k0 + akq];
        } else {
            int k  = tid >> 4;
            int nq = (tid & 15) * 4;
            pb = *(const float4*)&B[(size_t)(k0 + k) * ldb + n0 + nq];
        }
    };

    auto stos = [&]() {
        #pragma unroll
        for (int it = 0; it < 2; it++) {
            int row = arow0 + it * 64;
            As[row][akq + 0] = tf32r(pa[it].x); As[row][akq + 1] = tf32r(pa[it].y);
            As[row][akq + 2] = tf32r(pa[it].z); As[row][akq + 3] = tf32r(pa[it].w);
        }
        if (BNK) {
            int row = tid >> 2;
            Bs[row][akq + 0] = tf32r(pb.x); Bs[row][akq + 1] = tf32r(pb.y);
            Bs[row][akq + 2] = tf32r(pb.z); Bs[row][akq + 3] = tf32r(pb.w);
        } else {
            int k  = tid >> 4;
            int nq = (tid & 15) * 4;
            Bs[nq + 0][k] = tf32r(pb.x); Bs[nq + 1][k] = tf32r(pb.y);
            Bs[nq + 2][k] = tf32r(pb.z); Bs[nq + 3][k] = tf32r(pb.w);
        }
    };

    loadg(0);
    for (int k0 = 0; k0 < K; k0 += 16) {
        stos();
        __syncthreads();
        if (k0 + 16 < K) loadg(k0 + 16);

        #pragma unroll
        for (int ks = 0; ks < 16; ks += 8) {
            uint32_t a[2][4];
            #pragma unroll
            for (int mt = 0; mt < 2; mt++) {
                int r = wm + mt * 16 + grp;
                a[mt][0] = __float_as_uint(As[r    ][ks + qid]);
                a[mt][1] = __float_as_uint(As[r + 8][ks + qid]);
                a[mt][2] = __float_as_uint(As[r    ][ks + qid + 4]);
                a[mt][3] = __float_as_uint(As[r + 8][ks + qid + 4]);
            }
            #pragma unroll
            for (int nt = 0; nt < 4; nt++) {
                int nr = wn + nt * 8 + grp;
                uint32_t b0 = __float_as_uint(Bs[nr][ks + qid]);
                uint32_t b1 = __float_as_uint(Bs[nr][ks + qid + 4]);
                mma8(c[0][nt], a[0], b0, b1);
                mma8(c[1][nt], a[1], b0, b1);
            }
        }
        __syncthreads();
    }

    #pragma unroll
    for (int mt = 0; mt < 2; mt++) {
        int r = m0 + wm + mt * 16 + grp;
        #pragma unroll
        for (int nt = 0; nt < 4; nt++) {
            int cc = n0 + wn + nt * 8 + 2 * qid;
            float b0v = 0.f, b1v = 0.f;
            if (bias) { b0v = bias[cc]; b1v = bias[cc + 1]; }
            C[(size_t)r * ldc + cc]           = c[mt][nt][0] * scale + b0v;
            C[(size_t)r * ldc + cc + 1]       = c[mt][nt][1] * scale + b1v;
            C[(size_t)(r + 8) * ldc + cc]     = c[mt][nt][2] * scale + b0v;
            C[(size_t)(r + 8) * ldc + cc + 1] = c[mt][nt][3] * scale + b1v;
        }
    }
}

// ------------------------- GEMM wrappers -------------------------
// z = blockIdx.z + zbase: 0 mq=Q@Wq, 1 mk=K@Wk, 2 mv=V@Wv, 3 co=V@coW+cob
__global__ void proj_tgemm(int zbase,
                           const float* __restrict__ Q, const float* __restrict__ Kin,
                           const float* __restrict__ V,
                           const float* __restrict__ Wq, const float* __restrict__ Wk,
                           const float* __restrict__ Wv, const float* __restrict__ coW,
                           const float* __restrict__ cob)
{
    const int z = blockIdx.z + zbase;
    const float* A = (z == 0) ? Q : (z == 1) ? Kin : V;
    const float* B = (z == 0) ? Wq : (z == 1) ? Wk : (z == 2) ? Wv : coW;
    float* C = (z == 0) ? g_mq : (z == 1) ? g_mk : (z == 2) ? g_mv : g_co;
    const float* bias = (z == 3) ? cob : nullptr;
    tgemm_core<false, false>(A, nullptr, B, bias, C, HID_, HID_, AH_, AH_, 1.f,
                             blockIdx.y * 128, blockIdx.x * 64);
}

__global__ void pw_tgemm(const float* __restrict__ pww, const float* __restrict__ sepb)
{
    tgemm_core<true, false>(g_dw, nullptr, pww, sepb, g_mkc, HID_, HID_, HID_, AH_, 1.f,
                            blockIdx.y * 128, blockIdx.x * 64);
}

__global__ void score_tgemm(int bhbase)
{
    const int bh = blockIdx.z + bhbase;
    const int b = bh / HH, h = bh % HH;
    const float* A = g_mq + (size_t)b * SS * AH_ + h * DD;
    const float* B = g_mk + (size_t)b * SS * AH_ + h * DD;
    float* C = g_scores + (size_t)bh * SS * SS;
    tgemm_core<true, false>(A, nullptr, B, nullptr, C, DD, AH_, AH_, SS, 0.125f,
                            blockIdx.y * 128, blockIdx.x * 64);
}

__global__ void ctx_tgemm(float* __restrict__ out)
{
    const int bh = blockIdx.z;
    const int b = bh / HH, h = bh % HH;
    const float* A = g_scores + (size_t)bh * SS * SS;
    const float* B = g_mv + (size_t)b * SS * AH_ + h * DD;
    float* C = out + (size_t)b * SS * (2 * AH_) + h * DD;
    tgemm_core<false, false>(A, nullptr, B, nullptr, C, SS, SS, AH_, 2 * AH_, 1.f,
                             blockIdx.y * 128, 0);
}

// ck logits = (mkc .* mq) @ ckWp + ckbp
__global__ void ck_tgemm()
{
    tgemm_core<false, true>(g_mkc, g_mq, g_ckWp, g_ckbp, g_cklg, AH_, AH_, 64, 64, 1.f,
                            blockIdx.y * 128, 0);
}

// ------------------------- pad ckW/ckb to 64 cols -------------------------
__global__ void pad_ckW(const float* __restrict__ ckW, const float* __restrict__ ckb)
{
    int idx = blockIdx.x * blockDim.x + threadIdx.x;
    if (idx < AH_ * 64) {
        int k = idx >> 6, n = idx & 63;
        g_ckWp[idx] = (n < HH * KS_) ? ckW[k * (HH * KS_) + n] : 0.f;
    }
    if (idx < 64) g_ckbp[idx] = (idx < HH * KS_) ? ckb[idx] : 0.f;
}

// ------------------------- depthwise conv over seq dim of K -------------------------
__global__ void dwconv_kernel(const float* __restrict__ Kin, const float* __restrict__ dww)
{
    int idx = blockIdx.x * blockDim.x + threadIdx.x;
    if (idx >= BB * SS * HID_) return;
    int c = idx % HID_;
    int bs = idx / HID_;
    int s = bs % SS;
    int b = bs / SS;
    float acc = 0.f;
    #pragma unroll
    for (int k = 0; k < KS_; k++) {
        int sp = s + k - PAD_;
        float x = (sp >= 0 && sp < SS) ? Kin[(size_t)(b * SS + sp) * HID_ + c] : 0.f;
        acc += x * dww[c * KS_ + k];
    }
    g_dw[idx] = acc;
}

// ------------------------- dynamic conv output + ck softmax (second half of out) ----------
__global__ void conv_out_kernel(float* __restrict__ out)
{
    __shared__ float lg[HH * KS_];
    int bs = blockIdx.x;
    int b = bs / SS, s = bs % SS;
    int tid = threadIdx.x;   // 384
    if (tid < HH * KS_) lg[tid] = g_cklg[(size_t)bs * 64 + tid];
    __syncthreads();
    int h = tid / DD;

    float m = -1e30f;
    #pragma unroll
    for (int k = 0; k < KS_; k++) m = fmaxf(m, lg[h * KS_ + k]);
    float w[KS_], Z = 0.f;
    #pragma unroll
    for (int k = 0; k < KS_; k++) { w[k] = fexp(lg[h * KS_ + k] - m); Z += w[k]; }
    float iz = 1.f / Z;

    float acc = 0.f;
    #pragma unroll
    for (int k = 0; k < KS_; k++) {
        int sp = s + k - PAD_;
        if (sp >= 0 && sp < SS)
            acc += g_co[(size_t)(b * SS + sp) * AH_ + tid] * (w[k] * iz);
    }
    out[(size_t)bs * (2 * AH_) + AH_ + tid] = acc;
}

// ------------------------- td softmax (per batch) -------------------------
__global__ void tdsm_kernel(const float* __restrict__ td, const int* __restrict__ mask)
{
    __shared__ float red[256];
    int b = blockIdx.x, t = threadIdx.x;
    const float* tdr = td + b * SS;
    const int* mr = mask + b * SS;

    float ss = 0.f;
    #pragma unroll
    for (int c = 0; c < 4; c++) { float v = tdr[t + 256 * c]; ss += v * v; }
    red[t] = ss; __syncthreads();
    for (int o = 128; o > 0; o >>= 1) { if (t < o) red[t] += red[t + o]; __syncthreads(); }
    float inv = 1.f / fmaxf(sqrtf(red[0]), 1e-12f);
    __syncthreads();

    float x[4]; float m = -1e30f;
    #pragma unroll
    for (int c = 0; c < 4; c++) {
        int j = t + 256 * c;
        x[c] = mr[j] ? tdr[j] * inv : -1e4f;
        m = fmaxf(m, x[c]);
    }
    red[t] = m; __syncthreads();
    for (int o = 128; o > 0; o >>= 1) { if (t < o) red[t] = fmaxf(red[t], red[t + o]); __syncthreads(); }
    m = red[0]; __syncthreads();

    float zs = 0.f;
    #pragma unroll
    for (int c = 0; c < 4; c++) { x[c] = fexp(x[c] - m); zs += x[c]; }
    red[t] = zs; __syncthreads();
    for (int o = 128; o > 0; o >>= 1) { if (t < o) red[t] += red[t + o]; __syncthreads(); }
    float iz = 1.f / red[0];
    #pragma unroll
    for (int c = 0; c < 4; c++) g_tdsm[b * SS + t + 256 * c] = x[c] * iz;
}

// ------------------------- dist/softmax: warp per row, no block barriers ----------
__global__ void prob_kernel(int bhbase, const int* __restrict__ mask, const float* __restrict__ gammas)
{
    const int w = threadIdx.x >> 5, lane = threadIdx.x & 31;
    const int i = blockIdx.x * 8 + w;
    const int bh = blockIdx.y + bhbase;
    const int b = bh / HH, h = bh % HH;
    const unsigned FULL = 0xffffffffu;

    const float gamma = -log1pf(expf(gammas[h]));
    float* srow = g_scores + ((size_t)bh * SS + i) * SS;
    const int* mrow = mask + b * SS;

    float sj[8][4];
    unsigned mbits = 0;
    float m = -1e30f;
    #pragma unroll
    for (int c = 0; c < 8; c++) {
        float4 s4 = *(const float4*)&srow[c * 128 + lane * 4];
        int4   m4 = *(const int4*)&mrow[c * 128 + lane * 4];
        sj[c][0] = s4.x; sj[c][1] = s4.y; sj[c][2] = s4.z; sj[c][3] = s4.w;
        if (m4.x) { mbits |= 1u << (c * 4 + 0); m = fmaxf(m, s4.x); }
        if (m4.y) { mbits |= 1u << (c * 4 + 1); m = fmaxf(m, s4.y); }
        if (m4.z) { mbits |= 1u << (c * 4 + 2); m = fmaxf(m, s4.z); }
        if (m4.w) { mbits |= 1u << (c * 4 + 3); m = fmaxf(m, s4.w); }
    }
    #pragma unroll
    for (int o = 16; o > 0; o >>= 1) m = fmaxf(m, __shfl_xor_sync(FULL, m, o));

    float cum[8][4];
    float base = 0.f;
    #pragma unroll
    for (int c = 0; c < 8; c++) {
        float p[4]; float ls = 0.f;
        #pragma unroll
        for (int u = 0; u < 4; u++) {
            p[u] = ((mbits >> (c * 4 + u)) & 1u) ? fexp(sj[c][u] - m) : 0.f;
            ls += p[u];
        }
        float v = ls;
        #pragma unroll
        for (int o = 1; o < 32; o <<= 1) {
            float n = __shfl_up_sync(FULL, v, o);
            if (lane >= o) v += n;
        }
        float run = base + (v - ls);
        #pragma unroll
        for (int u = 0; u < 4; u++) { run += p[u]; cum[c][u] = run; }
        base += __shfl_sync(FULL, v, 31);
    }
    const float T = base;
    const float invT = 1.f / fmaxf(T, 1e-30f);

    float m2 = -1e30f;
    #pragma unroll
    for (int c = 0; c < 8; c++) {
        #pragma unroll
        for (int u = 0; u < 4; u++) {
            int j = c * 128 + lane * 4 + u;
            float rem = (T - cum[c][u]) * invT;
            float pos = fabsf((float)(j - i));
            float ds = fsqrt_(fmaxf(rem * pos, 0.f));
            float te = fminf(fmaxf(fexp(gamma * ds), 1e-5f), 1e5f);
            if (j < i) te -= g_tdsm[b * SS + j];
            float fv = ((mbits >> (c * 4 + u)) & 1u) ? sj[c][u] * te : -1e8f;
            sj[c][u] = fv;
            m2 = fmaxf(m2, fv);
        }
    }
    #pragma unroll
    for (int o = 16; o > 0; o >>= 1) m2 = fmaxf(m2, __shfl_xor_sync(FULL, m2, o));

    float zs = 0.f;
    #pragma unroll
    for (int c = 0; c < 8; c++) {
        #pragma unroll
        for (int u = 0; u < 4; u++) {
            float e = ((mbits >> (c * 4 + u)) & 1u) ? fexp(sj[c][u] - m2) : 0.f;
            sj[c][u] = e;
            zs += e;
        }
    }
    #pragma unroll
    for (int o = 16; o > 0; o >>= 1) zs += __shfl_xor_sync(FULL, zs, o);
    const float invZ = 1.f / zs;

    #pragma unroll
    for (int c = 0; c < 8; c++) {
        float4 o4;
        o4.x = sj[c][0] * invZ; o4.y = sj[c][1] * invZ;
        o4.z = sj[c][2] * invZ; o4.w = sj[c][3] * invZ;
        *(float4*)&srow[c * 128 + lane * 4] = o4;
    }
}

// ------------------------- launch (3-stream pipelined fork/join) ------
// NOTE: every cudaEventRecord precedes all cudaStreamWaitEvent calls on that
// event in host order — required for stream capture.
extern "C" void kernel_launch(void* const* d_in, const int* in_sizes, int n_in,
                              void* d_out, int out_size)
{
    (void)in_sizes; (void)n_in; (void)out_size;
    const float* Q      = (const float*)d_in[0];
    const float* K      = (const float*)d_in[1];
    const float* V      = (const float*)d_in[2];
    const float* td     = (const float*)d_in[3];
    const int*   mask   = (const int*)d_in[4];
    const float* Wq     = (const float*)d_in[5];
    const float* Wk     = (const float*)d_in[6];
    const float* Wv     = (const float*)d_in[7];
    const float* dww    = (const float*)d_in[8];
    const float* pww    = (const float*)d_in[9];
    const float* sepb   = (const float*)d_in[10];
    const float* ckW    = (const float*)d_in[11];
    const float* ckb    = (const float*)d_in[12];
    const float* coW    = (const float*)d_in[13];
    const float* cob    = (const float*)d_in[14];
    const float* gammas = (const float*)d_in[15];
    float* out = (float*)d_out;

    static cudaStream_t sB = nullptr, sC = nullptr;
    static cudaEvent_t evFork = nullptr, evQK = nullptr, evVco = nullptr, evTd = nullptr,
                       evS0 = nullptr, evS1 = nullptr, evP0 = nullptr, evP1 = nullptr,
                       evJoin = nullptr;
    if (!sB) {
        cudaStreamCreateWithFlags(&sB, cudaStreamNonBlocking);
        cudaStreamCreateWithFlags(&sC, cudaStreamNonBlocking);
        cudaEventCreateWithFlags(&evFork, cudaEventDisableTiming);
        cudaEventCreateWithFlags(&evQK,   cudaEventDisableTiming);
        cudaEventCreateWithFlags(&evVco,  cudaEventDisableTiming);
        cudaEventCreateWithFlags(&evTd,   cudaEventDisableTiming);
        cudaEventCreateWithFlags(&evS0,   cudaEventDisableTiming);
        cudaEventCreateWithFlags(&evS1,   cudaEventDisableTiming);
        cudaEventCreateWithFlags(&evP0,   cudaEventDisableTiming);
        cudaEventCreateWithFlags(&evP1,   cudaEventDisableTiming);
        cudaEventCreateWithFlags(&evJoin, cudaEventDisableTiming);
    }

    const int M = BB * SS;
    const int BH = BB * HH;        // 24
    const int HALF = BH / 2;       // 12

    // ---- fork side streams off the capture (default) stream
    cudaEventRecord(evFork, 0);
    cudaStreamWaitEvent(sB, evFork, 0);
    cudaStreamWaitEvent(sC, evFork, 0);

    // ---- main stream: Q/K projections FIRST (so evQK exists before sB waits on it)
    proj_tgemm<<<dim3(AH_ / 64, M / 128, 2), 256>>>(0, Q, K, V, Wq, Wk, Wv, coW, cob);
    cudaEventRecord(evQK, 0);

    // ---- side stream B: conv branch + V/co projections
    dwconv_kernel<<<(BB * SS * HID_ + 255) / 256, 256, 0, sB>>>(K, dww);
    tdsm_kernel<<<BB, 256, 0, sB>>>(td, mask);
    cudaEventRecord(evTd, sB);
    pad_ckW<<<(AH_ * 64 + 255) / 256, 256, 0, sB>>>(ckW, ckb);
    proj_tgemm<<<dim3(AH_ / 64, M / 128, 2), 256, 0, sB>>>(2, Q, K, V, Wq, Wk, Wv, coW, cob);
    cudaEventRecord(evVco, sB);
    pw_tgemm<<<dim3(AH_ / 64, M / 128), 256, 0, sB>>>(pww, sepb);
    cudaStreamWaitEvent(sB, evQK, 0);              // ck needs mq (evQK recorded above)
    ck_tgemm<<<dim3(1, M / 128), 256, 0, sB>>>();
    conv_out_kernel<<<BB * SS, AH_, 0, sB>>>(out);
    cudaEventRecord(evJoin, sB);

    // ---- main stream: chunked score
    score_tgemm<<<dim3(SS / 64, SS / 128, HALF), 256>>>(0);
    cudaEventRecord(evS0, 0);
    score_tgemm<<<dim3(SS / 64, SS / 128, HALF), 256>>>(HALF);
    cudaEventRecord(evS1, 0);

    // ---- stream C: chunked prob, overlapping with score chunk 1
    cudaStreamWaitEvent(sC, evTd, 0);
    cudaStreamWaitEvent(sC, evS0, 0);
    prob_kernel<<<dim3(SS / 8, HALF), 256, 0, sC>>>(0, mask, gammas);
    cudaEventRecord(evP0, sC);
    cudaStreamWaitEvent(sC, evS1, 0);
    prob_kernel<<<dim3(SS / 8, HALF), 256, 0, sC>>>(HALF, mask, gammas);
    cudaEventRecord(evP1, sC);

    // ---- main stream: ctx (needs all probs + mv)
    cudaStreamWaitEvent(0, evP0, 0);
    cudaStreamWaitEvent(0, evP1, 0);
    cudaStreamWaitEvent(0, evVco, 0);
    ctx_tgemm<<<dim3(1, SS / 128, BH), 256>>>(out);

    // ---- join side stream back into capture stream
    cudaStreamWaitEvent(0, evJoin, 0);
}

// round 14
// speedup vs baseline: 1.1375x; 1.1375x over previous
#include <cuda_runtime.h>
#include <cuda_fp16.h>
#include <math.h>
#include <stdint.h>

#define BB    4
#define SS    1024
#define HID_  768
#define HH    6
#define DD    64
#define AH_   384
#define KS_   9
#define PAD_  4

// ------------------------- scratch (static device mem) -------------------------
__device__ float g_mq [BB*SS*AH_];
__device__ float g_mk [BB*SS*AH_];
__device__ float g_mv [BB*SS*AH_];
__device__ float g_co [BB*SS*AH_];
__device__ float g_dw [BB*SS*HID_];
__device__ float g_mkc[BB*SS*AH_];
__device__ float g_cklg[BB*SS*64];     // ck logits, padded to 64 cols
__device__ float g_ckWp[AH_*64];       // ckW padded (384,54)->(384,64)
__device__ float g_ckbp[64];
__device__ float g_tdsm[BB*SS];
__device__ __half g_scores[(size_t)BB*HH*SS*SS];   // 50 MB; scores then probs in-place (fp16)

// ------------------------- fast math (FMA pipe, no MUFU) -------------------------
__device__ __forceinline__ float fexp(float x) {
    float t = x * 1.442695041f;
    t = fminf(fmaxf(t, -126.f), 126.f);
    float r  = t + 12582912.f;
    int   ei = __float_as_int(r) - 0x4B400000;
    float f  = t - (r - 12582912.f);
    float p = fmaf(f, 0.0013333558f, 0.0096181291f);
    p = fmaf(f, p, 0.0555041087f);
    p = fmaf(f, p, 0.2402265069f);
    p = fmaf(f, p, 0.6931471806f);
    p = fmaf(f, p, 1.0f);
    return p * __int_as_float((ei + 127) << 23);
}

__device__ __forceinline__ float fsqrt_(float x) {
    if (x <= 1.1754944e-38f) return 0.f;
    float y = __int_as_float(0x5f3759df - (__float_as_int(x) >> 1));
    y = y * fmaf(-0.5f * x * y, y, 1.5f);
    y = y * fmaf(-0.5f * x * y, y, 1.5f);
    return x * y;
}

// ------------------------- tf32 helpers -------------------------
__device__ __forceinline__ float tf32r(float x) {
    uint32_t r;
    asm("cvt.rna.tf32.f32 %0, %1;" : "=r"(r) : "f"(x));
    return __uint_as_float(r);
}

__device__ __forceinline__ void mma8(float* c, const uint32_t* a, uint32_t b0, uint32_t b1) {
    asm volatile("mma.sync.aligned.m16n8k8.row.col.f32.tf32.tf32.f32 "
        "{%0,%1,%2,%3}, {%4,%5,%6,%7}, {%8,%9}, {%0,%1,%2,%3};"
        : "+f"(c[0]), "+f"(c[1]), "+f"(c[2]), "+f"(c[3])
        : "r"(a[0]), "r"(a[1]), "r"(a[2]), "r"(a[3]), "r"(b0), "r"(b1));
}

// ------------------------- tf32 tensor-core GEMM core (128x64 tile) -------------------------
// 256 threads = 8 warps (4m x 2n), warp tile 32x32, k-step 16, reg-prefetch double buffer.
// AH16: A operand is fp16 (converted to tf32 at SMEM fill). CH16: C stored as fp16.
template<bool BNK, bool AMUL, bool AH16, bool CH16>
__device__ __forceinline__ void tgemm_core(
    const void* __restrict__ Av, const float* __restrict__ A2,
    const float* __restrict__ B,
    const float* __restrict__ bias, void* __restrict__ Cv,
    int K, int lda, int ldb, int ldc, float scale, int m0, int n0)
{
    __shared__ float As[128][20];
    __shared__ float Bs[64][20];
    const int tid = threadIdx.x;
    const int warp = tid >> 5, lane = tid & 31;
    const int wm = (warp >> 1) * 32;
    const int wn = (warp & 1) * 32;
    const int grp = lane >> 2, qid = lane & 3;

    const int arow0 = (tid >> 2);
    const int akq   = (tid & 3) * 4;

    float c[2][4][4];
    #pragma unroll
    for (int mt = 0; mt < 2; mt++)
        #pragma unroll
        for (int nt = 0; nt < 4; nt++)
            #pragma unroll
            for (int r = 0; r < 4; r++) c[mt][nt][r] = 0.f;

    float4 pa[2], pb;

    auto loadg = [&](int k0) {
        #pragma unroll
        for (int it = 0; it < 2; it++) {
            int row = arow0 + it * 64;
            if (AH16) {
                const __half* Ah = (const __half*)Av;
                uint2 raw = *(const uint2*)&Ah[(size_t)(m0 + row) * lda + k0 + akq];
                __half2 h01 = *(__half2*)&raw.x;
                __half2 h23 = *(__half2*)&raw.y;
                float2 f01 = __half22float2(h01);
                float2 f23 = __half22float2(h23);
                pa[it] = make_float4(f01.x, f01.y, f23.x, f23.y);
            } else {
                pa[it] = *(const float4*)&((const float*)Av)[(size_t)(m0 + row) * lda + k0 + akq];
                if (AMUL) {
                    float4 w = *(const float4*)&A2[(size_t)(m0 + row) * lda + k0 + akq];
                    pa[it].x *= w.x; pa[it].y *= w.y; pa[it].z *= w.z; pa[it].w *= w.w;
                }
            }
        }
        if (BNK) {
            int row = tid >> 2;
            pb = *(const float4*)&B[(size_t)(n0 + row) * ldb + k0 + akq];
        } else {
            int k  = tid >> 4;
            int nq = (tid & 15) * 4;
            pb = *(const float4*)&B[(size_t)(k0 + k) * ldb + n0 + nq];
        }
    };

    auto stos = [&]() {
        #pragma unroll
        for (int it = 0; it < 2; it++) {
            int row = arow0 + it * 64;
            As[row][akq + 0] = tf32r(pa[it].x); As[row][akq + 1] = tf32r(pa[it].y);
            As[row][akq + 2] = tf32r(pa[it].z); As[row][akq + 3] = tf32r(pa[it].w);
        }
        if (BNK) {
            int row = tid >> 2;
            Bs[row][akq + 0] = tf32r(pb.x); Bs[row][akq + 1] = tf32r(pb.y);
            Bs[row][akq + 2] = tf32r(pb.z); Bs[row][akq + 3] = tf32r(pb.w);
        } else {
            int k  = tid >> 4;
            int nq = (tid & 15) * 4;
            Bs[nq + 0][k] = tf32r(pb.x); Bs[nq + 1][k] = tf32r(pb.y);
            Bs[nq + 2][k] = tf32r(pb.z); Bs[nq + 3][k] = tf32r(pb.w);
        }
    };

    loadg(0);
    for (int k0 = 0; k0 < K; k0 += 16) {
        stos();
        __syncthreads();
        if (k0 + 16 < K) loadg(k0 + 16);

        #pragma unroll
        for (int ks = 0; ks < 16; ks += 8) {
            uint32_t a[2][4];
            #pragma unroll
            for (int mt = 0; mt < 2; mt++) {
                int r = wm + mt * 16 + grp;
                a[mt][0] = __float_as_uint(As[r    ][ks + qid]);
                a[mt][1] = __float_as_uint(As[r + 8][ks + qid]);
                a[mt][2] = __float_as_uint(As[r    ][ks + qid + 4]);
                a[mt][3] = __float_as_uint(As[r + 8][ks + qid + 4]);
            }
            #pragma unroll
            for (int nt = 0; nt < 4; nt++) {
                int nr = wn + nt * 8 + grp;
                uint32_t b0 = __float_as_uint(Bs[nr][ks + qid]);
                uint32_t b1 = __float_as_uint(Bs[nr][ks + qid + 4]);
                mma8(c[0][nt], a[0], b0, b1);
                mma8(c[1][nt], a[1], b0, b1);
            }
        }
        __syncthreads();
    }

    #pragma unroll
    for (int mt = 0; mt < 2; mt++) {
        int r = m0 + wm + mt * 16 + grp;
        #pragma unroll
        for (int nt = 0; nt < 4; nt++) {
            int cc = n0 + wn + nt * 8 + 2 * qid;
            float b0v = 0.f, b1v = 0.f;
            if (bias) { b0v = bias[cc]; b1v = bias[cc + 1]; }
            float v0 = c[mt][nt][0] * scale + b0v;
            float v1 = c[mt][nt][1] * scale + b1v;
            float v2 = c[mt][nt][2] * scale + b0v;
            float v3 = c[mt][nt][3] * scale + b1v;
            if (CH16) {
                __half* C = (__half*)Cv;
                *(__half2*)&C[(size_t)r * ldc + cc]       = __floats2half2_rn(v0, v1);
                *(__half2*)&C[(size_t)(r + 8) * ldc + cc] = __floats2half2_rn(v2, v3);
            } else {
                float* C = (float*)Cv;
                C[(size_t)r * ldc + cc]           = v0;
                C[(size_t)r * ldc + cc + 1]       = v1;
                C[(size_t)(r + 8) * ldc + cc]     = v2;
                C[(size_t)(r + 8) * ldc + cc + 1] = v3;
            }
        }
    }
}

// ------------------------- GEMM wrappers -------------------------
// z = blockIdx.z + zbase: 0 mq=Q@Wq, 1 mk=K@Wk, 2 mv=V@Wv, 3 co=V@coW+cob
__global__ void proj_tgemm(int zbase,
                           const float* __restrict__ Q, const float* __restrict__ Kin,
                           const float* __restrict__ V,
                           const float* __restrict__ Wq, const float* __restrict__ Wk,
                           const float* __restrict__ Wv, const float* __restrict__ coW,
                           const float* __restrict__ cob)
{
    const int z = blockIdx.z + zbase;
    const float* A = (z == 0) ? Q : (z == 1) ? Kin : V;
    const float* B = (z == 0) ? Wq : (z == 1) ? Wk : (z == 2) ? Wv : coW;
    float* C = (z == 0) ? g_mq : (z == 1) ? g_mk : (z == 2) ? g_mv : g_co;
    const float* bias = (z == 3) ? cob : nullptr;
    tgemm_core<false, false, false, false>(A, nullptr, B, bias, C, HID_, HID_, AH_, AH_, 1.f,
                                           blockIdx.y * 128, blockIdx.x * 64);
}

__global__ void pw_tgemm(const float* __restrict__ pww, const float* __restrict__ sepb)
{
    tgemm_core<true, false, false, false>(g_dw, nullptr, pww, sepb, g_mkc,
                                          HID_, HID_, HID_, AH_, 1.f,
                                          blockIdx.y * 128, blockIdx.x * 64);
}

__global__ void score_tgemm(int bhbase)
{
    const int bh = blockIdx.z + bhbase;
    const int b = bh / HH, h = bh % HH;
    const float* A = g_mq + (size_t)b * SS * AH_ + h * DD;
    const float* B = g_mk + (size_t)b * SS * AH_ + h * DD;
    __half* C = g_scores + (size_t)bh * SS * SS;
    tgemm_core<true, false, false, true>(A, nullptr, B, nullptr, C, DD, AH_, AH_, SS, 0.125f,
                                         blockIdx.y * 128, blockIdx.x * 64);
}

__global__ void ctx_tgemm(float* __restrict__ out)
{
    const int bh = blockIdx.z;
    const int b = bh / HH, h = bh % HH;
    const __half* A = g_scores + (size_t)bh * SS * SS;
    const float* B = g_mv + (size_t)b * SS * AH_ + h * DD;
    float* C = out + (size_t)b * SS * (2 * AH_) + h * DD;
    tgemm_core<false, false, true, false>(A, nullptr, B, nullptr, C, SS, SS, AH_, 2 * AH_, 1.f,
                                          blockIdx.y * 128, 0);
}

// ck logits = (mkc .* mq) @ ckWp + ckbp
__global__ void ck_tgemm()
{
    tgemm_core<false, true, false, false>(g_mkc, g_mq, g_ckWp, g_ckbp, g_cklg,
                                          AH_, AH_, 64, 64, 1.f,
                                          blockIdx.y * 128, 0);
}

// ------------------------- pad ckW/ckb to 64 cols -------------------------
__global__ void pad_ckW(const float* __restrict__ ckW, const float* __restrict__ ckb)
{
    int idx = blockIdx.x * blockDim.x + threadIdx.x;
    if (idx < AH_ * 64) {
        int k = idx >> 6, n = idx & 63;
        g_ckWp[idx] = (n < HH * KS_) ? ckW[k * (HH * KS_) + n] : 0.f;
    }
    if (idx < 64) g_ckbp[idx] = (idx < HH * KS_) ? ckb[idx] : 0.f;
}

// ------------------------- depthwise conv over seq dim of K -------------------------
__global__ void dwconv_kernel(const float* __restrict__ Kin, const float* __restrict__ dww)
{
    int idx = blockIdx.x * blockDim.x + threadIdx.x;
    if (idx >= BB * SS * HID_) return;
    int c = idx % HID_;
    int bs = idx / HID_;
    int s = bs % SS;
    int b = bs / SS;
    float acc = 0.f;
    #pragma unroll
    for (int k = 0; k < KS_; k++) {
        int sp = s + k - PAD_;
        float x = (sp >= 0 && sp < SS) ? Kin[(size_t)(b * SS + sp) * HID_ + c] : 0.f;
        acc += x * dww[c * KS_ + k];
    }
    g_dw[idx] = acc;
}

// ------------------------- dynamic conv output + ck softmax (second half of out) ----------
__global__ void conv_out_kernel(float* __restrict__ out)
{
    __shared__ float lg[HH * KS_];
    int bs = blockIdx.x;
    int b = bs / SS, s = bs % SS;
    int tid = threadIdx.x;   // 384
    if (tid < HH * KS_) lg[tid] = g_cklg[(size_t)bs * 64 + tid];
    __syncthreads();
    int h = tid / DD;

    float m = -1e30f;
    #pragma unroll
    for (int k = 0; k < KS_; k++) m = fmaxf(m, lg[h * KS_ + k]);
    float w[KS_], Z = 0.f;
    #pragma unroll
    for (int k = 0; k < KS_; k++) { w[k] = fexp(lg[h * KS_ + k] - m); Z += w[k]; }
    float iz = 1.f / Z;

    float acc = 0.f;
    #pragma unroll
    for (int k = 0; k < KS_; k++) {
        int sp = s + k - PAD_;
        if (sp >= 0 && sp < SS)
            acc += g_co[(size_t)(b * SS + sp) * AH_ + tid] * (w[k] * iz);
    }
    out[(size_t)bs * (2 * AH_) + AH_ + tid] = acc;
}

// ------------------------- td softmax (per batch) -------------------------
__global__ void tdsm_kernel(const float* __restrict__ td, const int* __restrict__ mask)
{
    __shared__ float red[256];
    int b = blockIdx.x, t = threadIdx.x;
    const float* tdr = td + b * SS;
    const int* mr = mask + b * SS;

    float ss = 0.f;
    #pragma unroll
    for (int c = 0; c < 4; c++) { float v = tdr[t + 256 * c]; ss += v * v; }
    red[t] = ss; __syncthreads();
    for (int o = 128; o > 0; o >>= 1) { if (t < o) red[t] += red[t + o]; __syncthreads(); }
    float inv = 1.f / fmaxf(sqrtf(red[0]), 1e-12f);
    __syncthreads();

    float x[4]; float m = -1e30f;
    #pragma unroll
    for (int c = 0; c < 4; c++) {
        int j = t + 256 * c;
        x[c] = mr[j] ? tdr[j] * inv : -1e4f;
        m = fmaxf(m, x[c]);
    }
    red[t] = m; __syncthreads();
    for (int o = 128; o > 0; o >>= 1) { if (t < o) red[t] = fmaxf(red[t], red[t + o]); __syncthreads(); }
    m = red[0]; __syncthreads();

    float zs = 0.f;
    #pragma unroll
    for (int c = 0; c < 4; c++) { x[c] = fexp(x[c] - m); zs += x[c]; }
    red[t] = zs; __syncthreads();
    for (int o = 128; o > 0; o >>= 1) { if (t < o) red[t] += red[t + o]; __syncthreads(); }
    float iz = 1.f / red[0];
    #pragma unroll
    for (int c = 0; c < 4; c++) g_tdsm[b * SS + t + 256 * c] = x[c] * iz;
}

// ------------------------- dist/softmax: warp per row, fp16 in/out ----------
__global__ void prob_kernel(int bhbase, const int* __restrict__ mask, const float* __restrict__ gammas)
{
    const int w = threadIdx.x >> 5, lane = threadIdx.x & 31;
    const int i = blockIdx.x * 8 + w;
    const int bh = blockIdx.y + bhbase;
    const int b = bh / HH, h = bh % HH;
    const unsigned FULL = 0xffffffffu;

    const float gamma = -log1pf(expf(gammas[h]));
    __half* srow = g_scores + ((size_t)bh * SS + i) * SS;
    const int* mrow = mask + b * SS;

    float sj[8][4];
    unsigned mbits = 0;
    float m = -1e30f;
    #pragma unroll
    for (int c = 0; c < 8; c++) {
        uint2 raw = *(const uint2*)&srow[c * 128 + lane * 4];
        float2 f01 = __half22float2(*(__half2*)&raw.x);
        float2 f23 = __half22float2(*(__half2*)&raw.y);
        int4   m4 = *(const int4*)&mrow[c * 128 + lane * 4];
        sj[c][0] = f01.x; sj[c][1] = f01.y; sj[c][2] = f23.x; sj[c][3] = f23.y;
        if (m4.x) { mbits |= 1u << (c * 4 + 0); m = fmaxf(m, sj[c][0]); }
        if (m4.y) { mbits |= 1u << (c * 4 + 1); m = fmaxf(m, sj[c][1]); }
        if (m4.z) { mbits |= 1u << (c * 4 + 2); m = fmaxf(m, sj[c][2]); }
        if (m4.w) { mbits |= 1u << (c * 4 + 3); m = fmaxf(m, sj[c][3]); }
    }
    #pragma unroll
    for (int o = 16; o > 0; o >>= 1) m = fmaxf(m, __shfl_xor_sync(FULL, m, o));

    float cum[8][4];
    float base = 0.f;
    #pragma unroll
    for (int c = 0; c < 8; c++) {
        float p[4]; float ls = 0.f;
        #pragma unroll
        for (int u = 0; u < 4; u++) {
            p[u] = ((mbits >> (c * 4 + u)) & 1u) ? fexp(sj[c][u] - m) : 0.f;
            ls += p[u];
        }
        float v = ls;
        #pragma unroll
        for (int o = 1; o < 32; o <<= 1) {
            float n = __shfl_up_sync(FULL, v, o);
            if (lane >= o) v += n;
        }
        float run = base + (v - ls);
        #pragma unroll
        for (int u = 0; u < 4; u++) { run += p[u]; cum[c][u] = run; }
        base += __shfl_sync(FULL, v, 31);
    }
    const float T = base;
    const float invT = 1.f / fmaxf(T, 1e-30f);

    float m2 = -1e30f;
    #pragma unroll
    for (int c = 0; c < 8; c++) {
        #pragma unroll
        for (int u = 0; u < 4; u++) {
            int j = c * 128 + lane * 4 + u;
            float rem = (T - cum[c][u]) * invT;
            float pos = fabsf((float)(j - i));
            float ds = fsqrt_(fmaxf(rem * pos, 0.f));
            float te = fminf(fmaxf(fexp(gamma * ds), 1e-5f), 1e5f);
            if (j < i) te -= g_tdsm[b * SS + j];
            float fv = ((mbits >> (c * 4 + u)) & 1u) ? sj[c][u] * te : -1e8f;
            sj[c][u] = fv;
            m2 = fmaxf(m2, fv);
        }
    }
    #pragma unroll
    for (int o = 16; o > 0; o >>= 1) m2 = fmaxf(m2, __shfl_xor_sync(FULL, m2, o));

    float zs = 0.f;
    #pragma unroll
    for (int c = 0; c < 8; c++) {
        #pragma unroll
        for (int u = 0; u < 4; u++) {
            float e = ((mbits >> (c * 4 + u)) & 1u) ? fexp(sj[c][u] - m2) : 0.f;
            sj[c][u] = e;
            zs += e;
        }
    }
    #pragma unroll
    for (int o = 16; o > 0; o >>= 1) zs += __shfl_xor_sync(FULL, zs, o);
    const float invZ = 1.f / zs;

    #pragma unroll
    for (int c = 0; c < 8; c++) {
        uint2 raw;
        *(__half2*)&raw.x = __floats2half2_rn(sj[c][0] * invZ, sj[c][1] * invZ);
        *(__half2*)&raw.y = __floats2half2_rn(sj[c][2] * invZ, sj[c][3] * invZ);
        *(uint2*)&srow[c * 128 + lane * 4] = raw;
    }
}

// ------------------------- launch (3-stream pipelined fork/join) ------
extern "C" void kernel_launch(void* const* d_in, const int* in_sizes, int n_in,
                              void* d_out, int out_size)
{
    (void)in_sizes; (void)n_in; (void)out_size;
    const float* Q      = (const float*)d_in[0];
    const float* K      = (const float*)d_in[1];
    const float* V      = (const float*)d_in[2];
    const float* td     = (const float*)d_in[3];
    const int*   mask   = (const int*)d_in[4];
    const float* Wq     = (const float*)d_in[5];
    const float* Wk     = (const float*)d_in[6];
    const float* Wv     = (const float*)d_in[7];
    const float* dww    = (const float*)d_in[8];
    const float* pww    = (const float*)d_in[9];
    const float* sepb   = (const float*)d_in[10];
    const float* ckW    = (const float*)d_in[11];
    const float* ckb    = (const float*)d_in[12];
    const float* coW    = (const float*)d_in[13];
    const float* cob    = (const float*)d_in[14];
    const float* gammas = (const float*)d_in[15];
    float* out = (float*)d_out;

    static cudaStream_t sB = nullptr, sC = nullptr;
    static cudaEvent_t evFork = nullptr, evQK = nullptr, evVco = nullptr, evTd = nullptr,
                       evS0 = nullptr, evS1 = nullptr, evP0 = nullptr, evP1 = nullptr,
                       evJoin = nullptr;
    if (!sB) {
        cudaStreamCreateWithFlags(&sB, cudaStreamNonBlocking);
        cudaStreamCreateWithFlags(&sC, cudaStreamNonBlocking);
        cudaEventCreateWithFlags(&evFork, cudaEventDisableTiming);
        cudaEventCreateWithFlags(&evQK,   cudaEventDisableTiming);
        cudaEventCreateWithFlags(&evVco,  cudaEventDisableTiming);
        cudaEventCreateWithFlags(&evTd,   cudaEventDisableTiming);
        cudaEventCreateWithFlags(&evS0,   cudaEventDisableTiming);
        cudaEventCreateWithFlags(&evS1,   cudaEventDisableTiming);
        cudaEventCreateWithFlags(&evP0,   cudaEventDisableTiming);
        cudaEventCreateWithFlags(&evP1,   cudaEventDisableTiming);
        cudaEventCreateWithFlags(&evJoin, cudaEventDisableTiming);
    }

    const int M = BB * SS;
    const int BH = BB * HH;        // 24
    const int HALF = BH / 2;       // 12

    // ---- fork side streams off the capture (default) stream
    cudaEventRecord(evFork, 0);
    cudaStreamWaitEvent(sB, evFork, 0);
    cudaStreamWaitEvent(sC, evFork, 0);

    // ---- main stream: Q/K projections FIRST (so evQK exists before sB waits on it)
    proj_tgemm<<<dim3(AH_ / 64, M / 128, 2), 256>>>(0, Q, K, V, Wq, Wk, Wv, coW, cob);
    cudaEventRecord(evQK, 0);

    // ---- side stream B: conv branch + V/co projections
    dwconv_kernel<<<(BB * SS * HID_ + 255) / 256, 256, 0, sB>>>(K, dww);
    tdsm_kernel<<<BB, 256, 0, sB>>>(td, mask);
    cudaEventRecord(evTd, sB);
    pad_ckW<<<(AH_ * 64 + 255) / 256, 256, 0, sB>>>(ckW, ckb);
    proj_tgemm<<<dim3(AH_ / 64, M / 128, 2), 256, 0, sB>>>(2, Q, K, V, Wq, Wk, Wv, coW, cob);
    cudaEventRecord(evVco, sB);
    pw_tgemm<<<dim3(AH_ / 64, M / 128), 256, 0, sB>>>(pww, sepb);
    cudaStreamWaitEvent(sB, evQK, 0);              // ck needs mq
    ck_tgemm<<<dim3(1, M / 128), 256, 0, sB>>>();
    conv_out_kernel<<<BB * SS, AH_, 0, sB>>>(out);
    cudaEventRecord(evJoin, sB);

    // ---- main stream: chunked score
    score_tgemm<<<dim3(SS / 64, SS / 128, HALF), 256>>>(0);
    cudaEventRecord(evS0, 0);
    score_tgemm<<<dim3(SS / 64, SS / 128, HALF), 256>>>(HALF);
    cudaEventRecord(evS1, 0);

    // ---- stream C: chunked prob, overlapping with score chunk 1
    cudaStreamWaitEvent(sC, evTd, 0);
    cudaStreamWaitEvent(sC, evS0, 0);
    prob_kernel<<<dim3(SS / 8, HALF), 256, 0, sC>>>(0, mask, gammas);
    cudaEventRecord(evP0, sC);
    cudaStreamWaitEvent(sC, evS1, 0);
    prob_kernel<<<dim3(SS / 8, HALF), 256, 0, sC>>>(HALF, mask, gammas);
    cudaEventRecord(evP1, sC);

    // ---- main stream: ctx (needs all probs + mv)
    cudaStreamWaitEvent(0, evP0, 0);
    cudaStreamWaitEvent(0, evP1, 0);
    cudaStreamWaitEvent(0, evVco, 0);
    ctx_tgemm<<<dim3(1, SS / 128, BH), 256>>>(out);

    // ---- join side stream back into capture stream
    cudaStreamWaitEvent(0, evJoin, 0);
}